// round 16
// baseline (speedup 1.0000x reference)
#include <cuda_runtime.h>
#include <cuda_fp16.h>
#include <math.h>
#include <stdint.h>

// ---------------------------------------------------------------------------
// Problem constants
// ---------------------------------------------------------------------------
constexpr int Bc = 8;
constexpr int Sc = 4096;
constexpr int Ic = 256;
constexpr int Kc = 512;      // fan_in
constexpr int Nc = 1536;     // 2*OUT*3
constexpr int Mc = Bc * Sc;  // 32768
constexpr int OUTC = 256;
constexpr int DCH = 512;     // 2*OUT

// scan chunking
constexpr int CHUNK = 64;
constexpr int NCH = Sc / CHUNK;  // 64

// hybrid split: N-blocks [0,9) -> fp16 HMMA path, [9,12) -> fp32 FFMA path
constexpr int NHB = 9;

// ---------------------------------------------------------------------------
// Device scratch
// ---------------------------------------------------------------------------
__device__ float d_g[(size_t)Mc * Nc];      // activated gates (192 MB)
__device__ __half d_xh[(size_t)Mc * Ic];    // fp16 x (16.8 MB)
__device__ __half d_wh[(size_t)Nc * Kc];    // fp16 W (1.5 MB)
__device__ float d_F[Bc * NCH * DCH];
__device__ float d_C[Bc * NCH * DCH];
__device__ float d_cin[Bc * NCH * DCH];

// ---------------------------------------------------------------------------
// Helpers
// ---------------------------------------------------------------------------
__device__ __forceinline__ float sigm(float v) { return 1.f / (1.f + expf(-v)); }

__device__ __forceinline__ void mma_f16(float* c, const uint32_t* a,
                                        const uint32_t* b) {
    asm volatile(
        "mma.sync.aligned.m16n8k16.row.col.f32.f16.f16.f32 "
        "{%0,%1,%2,%3}, {%4,%5,%6,%7}, {%8,%9}, {%0,%1,%2,%3};"
        : "+f"(c[0]), "+f"(c[1]), "+f"(c[2]), "+f"(c[3])
        : "r"(a[0]), "r"(a[1]), "r"(a[2]), "r"(a[3]), "r"(b[0]), "r"(b[1]));
}

__device__ __forceinline__ void cpasync16(uint32_t dst, const void* src,
                                          int src_bytes) {
    asm volatile("cp.async.cg.shared.global [%0], [%1], 16, %2;"
                 :: "r"(dst), "l"(src), "r"(src_bytes) : "memory");
}
__device__ __forceinline__ void cp_commit() {
    asm volatile("cp.async.commit_group;" ::: "memory");
}

// ---------------------------------------------------------------------------
// Convert inputs to fp16 (rn). float4 in -> 4 halfs out.
// ---------------------------------------------------------------------------
__global__ __launch_bounds__(256) void conv_x(const float* __restrict__ x) {
    size_t i = ((size_t)blockIdx.x * 256 + threadIdx.x) * 4;
    float4 v = *(const float4*)(x + i);
    *(__half2*)(d_xh + i) = __floats2half2_rn(v.x, v.y);
    *(__half2*)(d_xh + i + 2) = __floats2half2_rn(v.z, v.w);
}

__global__ __launch_bounds__(256) void conv_w(const float* __restrict__ W) {
    size_t i = ((size_t)blockIdx.x * 256 + threadIdx.x) * 4;
    float4 v = *(const float4*)(W + i);
    *(__half2*)(d_wh + i) = __floats2half2_rn(v.x, v.y);
    *(__half2*)(d_wh + i + 2) = __floats2half2_rn(v.z, v.w);
}

// ---------------------------------------------------------------------------
// Path A (bn < 9): fp16 mma.sync m16n8k16, fp32 accumulate (R15, proven).
// SMEM: As half[2][128][40] at 0 (20480 B), Bs at +20480 (total 40960).
// ---------------------------------------------------------------------------
constexpr int BM = 128;
constexpr int BN = 128;
constexpr int BKH = 32;          // k-halfs per stage
constexpr int KPH = 40;          // padded row stride (halfs); 80B rows
constexpr int KTH = Kc / BKH;    // 16 k-iterations

__device__ __forceinline__ void hmma_path(char* smraw,
                                          const float* __restrict__ bias) {
    __half* As = (__half*)smraw;             // [2][128][40]
    __half* Bs = (__half*)(smraw + 20480);   // [2][128][40]

    const int tid = threadIdx.x;
    const int warp = tid >> 5, lane = tid & 31;
    const int g = lane >> 2, t = lane & 3;
    const int wm = (warp >> 1) * 32;
    const int wn = (warp & 1) * 64;
    const int bm = blockIdx.y * BM;
    const int bn = blockIdx.x * BN;

    float acc[2][8][4];
#pragma unroll
    for (int i = 0; i < 2; i++)
#pragma unroll
        for (int j = 0; j < 8; j++)
#pragma unroll
            for (int q = 0; q < 4; q++) acc[i][j][q] = 0.f;

    uint32_t sbA = (uint32_t)__cvta_generic_to_shared(As);
    uint32_t sbB = (uint32_t)__cvta_generic_to_shared(Bs);

    auto load_stage = [&](int st, int kt) {
        int k0 = kt * BKH;
#pragma unroll
        for (int i = 0; i < 2; i++) {
            int id = tid + i * 256;          // 0..511
            int row = id >> 2, c = id & 3;   // row 0..127, chunk 0..3 (8 halfs)
            int m = bm + row;
            int kk = k0 + c * 8;
            {
                bool zero = ((m & (Sc - 1)) == 0) && (kk < 256);
                const __half* src =
                    zero ? d_xh : (d_xh + (size_t)(m - 1) * Ic + kk);
                cpasync16(sbA + (uint32_t)(st * BM * KPH + row * KPH + c * 8) * 2,
                          src, zero ? 0 : 16);
            }
            {
                const __half* src = d_wh + (size_t)(bn + row) * Kc + kk;
                cpasync16(sbB + (uint32_t)(st * BN * KPH + row * KPH + c * 8) * 2,
                          src, 16);
            }
        }
        cp_commit();
    };

    load_stage(0, 0);

    for (int kt = 0; kt < KTH; kt++) {
        int st = kt & 1;
        if (kt + 1 < KTH) {
            load_stage(st ^ 1, kt + 1);
            asm volatile("cp.async.wait_group 1;" ::: "memory");
        } else {
            asm volatile("cp.async.wait_group 0;" ::: "memory");
        }
        __syncthreads();

#pragma unroll
        for (int ks = 0; ks < 2; ks++) {
            int kb = ks * 16;
            uint32_t a[2][4], b[8][2];
#pragma unroll
            for (int i = 0; i < 2; i++) {
                int r0 = wm + i * 16;
                const __half* base = As + st * BM * KPH;
                a[i][0] = *(const uint32_t*)(base + (r0 + g) * KPH + kb + 2 * t);
                a[i][1] = *(const uint32_t*)(base + (r0 + g + 8) * KPH + kb + 2 * t);
                a[i][2] = *(const uint32_t*)(base + (r0 + g) * KPH + kb + 2 * t + 8);
                a[i][3] = *(const uint32_t*)(base + (r0 + g + 8) * KPH + kb + 2 * t + 8);
            }
#pragma unroll
            for (int j = 0; j < 8; j++) {
                int n0 = wn + j * 8;
                const __half* base = Bs + st * BN * KPH;
                b[j][0] = *(const uint32_t*)(base + (n0 + g) * KPH + kb + 2 * t);
                b[j][1] = *(const uint32_t*)(base + (n0 + g) * KPH + kb + 2 * t + 8);
            }
#pragma unroll
            for (int i = 0; i < 2; i++)
#pragma unroll
                for (int j = 0; j < 8; j++) mma_f16(acc[i][j], a[i], b[j]);
        }
        __syncthreads();
    }

    const bool is_z = (bn < 512);
#pragma unroll
    for (int i = 0; i < 2; i++) {
#pragma unroll
        for (int j = 0; j < 8; j++) {
            int col = bn + wn + j * 8 + 2 * t;
            float b0 = __ldg(bias + col), b1 = __ldg(bias + col + 1);
            int r0 = bm + wm + i * 16 + g;
            float2 v;
            v.x = acc[i][j][0] + b0;
            v.y = acc[i][j][1] + b1;
            v.x = is_z ? tanhf(v.x) : sigm(v.x);
            v.y = is_z ? tanhf(v.y) : sigm(v.y);
            *(float2*)(d_g + (size_t)r0 * Nc + col) = v;
            v.x = acc[i][j][2] + b0;
            v.y = acc[i][j][3] + b1;
            v.x = is_z ? tanhf(v.x) : sigm(v.x);
            v.y = is_z ? tanhf(v.y) : sigm(v.y);
            *(float2*)(d_g + (size_t)(r0 + 8) * Nc + col) = v;
        }
    }
}

// ---------------------------------------------------------------------------
// Path B (bn >= 9): fp32 SIMT FFMA SGEMM (R1, proven; o-gate cols, sigmoid).
// SMEM: As float[2][16][132] at 0 (16896 B), Bs at +16896 (total 33792).
// ---------------------------------------------------------------------------
__device__ __forceinline__ void ffma_path(char* smraw,
                                          const float* __restrict__ x,
                                          const float* __restrict__ W,
                                          const float* __restrict__ bias) {
    float* As = (float*)smraw;               // [2][16][132]
    float* Bs = (float*)(smraw + 16896);     // [2][16][132]

    const int tid = threadIdx.x;
    const int bm = blockIdx.y * 128;
    const int bn = blockIdx.x * 128;         // >= 1152: sigmoid region
    const int ty = tid >> 4, tx = tid & 15;

    float acc[8][8];
#pragma unroll
    for (int i = 0; i < 8; i++)
#pragma unroll
        for (int j = 0; j < 8; j++) acc[i][j] = 0.f;

    float4 fa[2], fb[2];
    auto fetch = [&](int k0) {
#pragma unroll
        for (int i = 0; i < 2; i++) {
            int v = tid + i * 256;
            int row = v >> 2;
            int k = k0 + (v & 3) * 4;
            int m = bm + row;
            if (k < 256 && ((m & (Sc - 1)) == 0)) {
                fa[i] = make_float4(0.f, 0.f, 0.f, 0.f);
            } else {
                fa[i] = *(const float4*)(x + (size_t)m * Ic + (k - 256));
            }
            fb[i] = *(const float4*)(W + (size_t)(bn + row) * Kc + k);
        }
    };
    auto store = [&](int st) {
        float* A = As + st * 2112;
        float* B = Bs + st * 2112;
#pragma unroll
        for (int i = 0; i < 2; i++) {
            int v = tid + i * 256;
            int row = v >> 2;
            int kq = (v & 3) * 4;
            A[(kq + 0) * 132 + row] = fa[i].x;
            A[(kq + 1) * 132 + row] = fa[i].y;
            A[(kq + 2) * 132 + row] = fa[i].z;
            A[(kq + 3) * 132 + row] = fa[i].w;
            B[(kq + 0) * 132 + row] = fb[i].x;
            B[(kq + 1) * 132 + row] = fb[i].y;
            B[(kq + 2) * 132 + row] = fb[i].z;
            B[(kq + 3) * 132 + row] = fb[i].w;
        }
    };

    fetch(0);
    store(0);
    __syncthreads();

    constexpr int KT = Kc / 16;  // 32
    for (int kt = 0; kt < KT; kt++) {
        int cb = kt & 1;
        if (kt + 1 < KT) fetch((kt + 1) * 16);

#pragma unroll
        for (int kk = 0; kk < 16; kk++) {
            float a[8], b[8];
#pragma unroll
            for (int i = 0; i < 8; i++) a[i] = As[cb * 2112 + kk * 132 + ty * 8 + i];
#pragma unroll
            for (int j = 0; j < 8; j++) b[j] = Bs[cb * 2112 + kk * 132 + tx * 8 + j];
#pragma unroll
            for (int i = 0; i < 8; i++)
#pragma unroll
                for (int j = 0; j < 8; j++) acc[i][j] = fmaf(a[i], b[j], acc[i][j]);
        }

        if (kt + 1 < KT) store(cb ^ 1);
        __syncthreads();
    }

    float bcol[8];
#pragma unroll
    for (int j = 0; j < 8; j++) bcol[j] = bias[bn + tx * 8 + j];

#pragma unroll
    for (int i = 0; i < 8; i++) {
        int m = bm + ty * 8 + i;
        size_t rowoff = (size_t)m * Nc + bn;
#pragma unroll
        for (int jj = 0; jj < 2; jj++) {
            float4 vv;
            vv.x = sigm(acc[i][jj * 4 + 0] + bcol[jj * 4 + 0]);
            vv.y = sigm(acc[i][jj * 4 + 1] + bcol[jj * 4 + 1]);
            vv.z = sigm(acc[i][jj * 4 + 2] + bcol[jj * 4 + 2]);
            vv.w = sigm(acc[i][jj * 4 + 3] + bcol[jj * 4 + 3]);
            *(float4*)(d_g + rowoff + tx * 8 + jj * 4) = vv;
        }
    }
}

// ---------------------------------------------------------------------------
// Hybrid GEMM: tensor pipe (fp16 HMMA) and fma pipe (fp32 FFMA) run in
// parallel on co-resident CTAs. 2 CTAs/SM enforced.
// ---------------------------------------------------------------------------
__global__ __launch_bounds__(256, 2) void gemm_hybrid(
    const float* __restrict__ x, const float* __restrict__ W,
    const float* __restrict__ bias) {
    __shared__ __align__(16) char smraw[40960];
    if (blockIdx.x < NHB) hmma_path(smraw, bias);
    else                  ffma_path(smraw, x, W, bias);
}

// ---------------------------------------------------------------------------
// Scans (chunk-parallel linear recurrence), CHUNK=64
// ---------------------------------------------------------------------------
__global__ __launch_bounds__(512) void scan_chunk() {
    int dirch = threadIdx.x;
    int b = blockIdx.x >> 6;
    int ck = blockIdx.x & (NCH - 1);
    bool bwd = dirch >= OUTC;
    int base = ck * CHUNK;

    float c = 0.f, F = 1.f;
#pragma unroll 8
    for (int t = 0; t < CHUNK; t++) {
        int s = bwd ? (base + CHUNK - 1 - t) : (base + t);
        size_t row = (size_t)(b * Sc + s) * Nc;
        float z = d_g[row + dirch];
        float f = d_g[row + DCH + dirch];
        c = f * c + (1.f - f) * z;
        F *= f;
    }
    int idx = (b * NCH + ck) * DCH + dirch;
    d_F[idx] = F;
    d_C[idx] = c;
}

__global__ __launch_bounds__(512) void scan_heads() {
    int dirch = threadIdx.x;
    int b = blockIdx.x;
    bool bwd = dirch >= OUTC;

    float c = 0.f;
#pragma unroll
    for (int i = 0; i < NCH; i++) {
        int ck = bwd ? (NCH - 1 - i) : i;
        int idx = (b * NCH + ck) * DCH + dirch;
        d_cin[idx] = c;
        c = d_F[idx] * c + d_C[idx];
    }
}

__global__ __launch_bounds__(512) void scan_final(float* __restrict__ out) {
    int dirch = threadIdx.x;
    int b = blockIdx.x >> 6;
    int ck = blockIdx.x & (NCH - 1);
    bool bwd = dirch >= OUTC;
    int base = ck * CHUNK;

    float c = d_cin[(b * NCH + ck) * DCH + dirch];
#pragma unroll 8
    for (int t = 0; t < CHUNK; t++) {
        int s = bwd ? (base + CHUNK - 1 - t) : (base + t);
        size_t row = (size_t)(b * Sc + s);
        const float* gr = d_g + row * Nc;
        float z = gr[dirch];
        float f = gr[DCH + dirch];
        float o = gr[2 * DCH + dirch];
        c = f * c + (1.f - f) * z;
        out[row * DCH + dirch] = o * c;
    }
}

// ---------------------------------------------------------------------------
extern "C" void kernel_launch(void* const* d_in, const int* in_sizes, int n_in,
                              void* d_out, int out_size) {
    const float* x = (const float*)d_in[0];
    const float* W = (const float*)d_in[1];
    const float* bias = (const float*)d_in[2];
    float* out = (float*)d_out;

    conv_x<<<(Mc * Ic) / (256 * 4), 256>>>(x);        // 8192 blocks
    conv_w<<<(Nc * Kc) / (256 * 4), 256>>>(W);        // 768 blocks

    dim3 gg(Nc / BN, Mc / BM);  // (12, 256)
    gemm_hybrid<<<gg, 256>>>(x, W, bias);

    scan_chunk<<<Bc * NCH, 512>>>();
    scan_heads<<<Bc, 512>>>();
    scan_final<<<Bc * NCH, 512>>>(out);
}

// round 17
// speedup vs baseline: 2.7128x; 2.7128x over previous
#include <cuda_runtime.h>
#include <cuda_fp16.h>
#include <math.h>
#include <stdint.h>

// ---------------------------------------------------------------------------
// Problem constants
// ---------------------------------------------------------------------------
constexpr int Bc = 8;
constexpr int Sc = 4096;
constexpr int Ic = 256;
constexpr int Kc = 512;      // fan_in
constexpr int Nc = 1536;     // 2*OUT*3
constexpr int Mc = Bc * Sc;  // 32768
constexpr int OUTC = 256;
constexpr int DCH = 512;     // 2*OUT

// scan chunking
constexpr int CHUNK = 64;
constexpr int NCH = Sc / CHUNK;  // 64

// ---------------------------------------------------------------------------
// Device scratch
// ---------------------------------------------------------------------------
__device__ float d_g[(size_t)Mc * Nc];      // activated gates (192 MB)
__device__ __half d_xh[(size_t)Mc * Ic];    // fp16 x (16.8 MB)
__device__ __half d_wh[(size_t)Nc * Kc];    // fp16 W (1.5 MB)
__device__ float d_F[Bc * NCH * DCH];
__device__ float d_C[Bc * NCH * DCH];
__device__ float d_cin[Bc * NCH * DCH];

// ---------------------------------------------------------------------------
// Helpers
// ---------------------------------------------------------------------------
__device__ __forceinline__ float sigm(float v) { return 1.f / (1.f + expf(-v)); }

__device__ __forceinline__ void mma_f16(float* c, const uint32_t* a,
                                        const uint32_t* b) {
    asm volatile(
        "mma.sync.aligned.m16n8k16.row.col.f32.f16.f16.f32 "
        "{%0,%1,%2,%3}, {%4,%5,%6,%7}, {%8,%9}, {%0,%1,%2,%3};"
        : "+f"(c[0]), "+f"(c[1]), "+f"(c[2]), "+f"(c[3])
        : "r"(a[0]), "r"(a[1]), "r"(a[2]), "r"(a[3]), "r"(b[0]), "r"(b[1]));
}

__device__ __forceinline__ void cpasync16(uint32_t dst, const void* src,
                                          int src_bytes) {
    asm volatile("cp.async.cg.shared.global [%0], [%1], 16, %2;"
                 :: "r"(dst), "l"(src), "r"(src_bytes) : "memory");
}
__device__ __forceinline__ void cp_commit() {
    asm volatile("cp.async.commit_group;" ::: "memory");
}

// ---------------------------------------------------------------------------
// Convert inputs to fp16 (rn). float4 in -> 4 halfs out.
// ---------------------------------------------------------------------------
__global__ __launch_bounds__(256) void conv_x(const float* __restrict__ x) {
    size_t i = ((size_t)blockIdx.x * 256 + threadIdx.x) * 4;
    float4 v = *(const float4*)(x + i);
    *(__half2*)(d_xh + i) = __floats2half2_rn(v.x, v.y);
    *(__half2*)(d_xh + i + 2) = __floats2half2_rn(v.z, v.w);
}

__global__ __launch_bounds__(256) void conv_w(const float* __restrict__ W) {
    size_t i = ((size_t)blockIdx.x * 256 + threadIdx.x) * 4;
    float4 v = *(const float4*)(W + i);
    *(__half2*)(d_wh + i) = __floats2half2_rn(v.x, v.y);
    *(__half2*)(d_wh + i + 2) = __floats2half2_rn(v.z, v.w);
}

// ---------------------------------------------------------------------------
// fp16 mma.sync m16n8k16 GEMM: d_g = act(A @ W^T + bias), fp32 accumulate.
// A[m][k] = xh[(m-1)*256 + k]  (k in [0,512)), zeroed when s==0 && k<256.
// Tile 128x128, BK=32 halfs, KT=16. 256 threads (8 warps, 4x2), warp 32x64.
// 2 CTAs/SM: co-resident CTAs cover each other's load-tail + barrier windows.
// ---------------------------------------------------------------------------
constexpr int BM = 128;
constexpr int BN = 128;
constexpr int BKH = 32;          // k-halfs per stage
constexpr int KPH = BKH + 8;     // padded row stride (halfs); 80B rows
constexpr int KT = Kc / BKH;     // 16 k-iterations

__global__ __launch_bounds__(256, 2) void gemm_mma(const float* __restrict__ bias) {
    __shared__ __half As[2][BM][KPH];   // 20480 B
    __shared__ __half Bs[2][BN][KPH];   // 20480 B  (total 40 KB; 2 CTAs = 80 KB/SM)

    const int tid = threadIdx.x;
    const int warp = tid >> 5, lane = tid & 31;
    const int g = lane >> 2, t = lane & 3;
    const int wm = (warp >> 1) * 32;   // warp M offset in tile
    const int wn = (warp & 1) * 64;    // warp N offset in tile
    const int bm = blockIdx.y * BM;
    const int bn = blockIdx.x * BN;

    float acc[2][8][4];
#pragma unroll
    for (int i = 0; i < 2; i++)
#pragma unroll
        for (int j = 0; j < 8; j++)
#pragma unroll
            for (int q = 0; q < 4; q++) acc[i][j][q] = 0.f;

    uint32_t sbA = (uint32_t)__cvta_generic_to_shared(&As[0][0][0]);
    uint32_t sbB = (uint32_t)__cvta_generic_to_shared(&Bs[0][0][0]);

    // stage loader: per operand 128 rows x 32 halfs = 128 rows x 4 16B-chunks
    auto load_stage = [&](int st, int kt) {
        int k0 = kt * BKH;
#pragma unroll
        for (int i = 0; i < 2; i++) {
            int id = tid + i * 256;          // 0..511
            int row = id >> 2, c = id & 3;   // row 0..127, chunk 0..3 (8 halfs)
            int m = bm + row;
            int kk = k0 + c * 8;
            {
                bool zero = ((m & (Sc - 1)) == 0) && (kk < 256);
                const __half* src =
                    zero ? d_xh : (d_xh + (size_t)(m - 1) * Ic + kk);
                cpasync16(sbA + (uint32_t)(st * BM * KPH + row * KPH + c * 8) * 2,
                          src, zero ? 0 : 16);
            }
            {
                const __half* src = d_wh + (size_t)(bn + row) * Kc + kk;
                cpasync16(sbB + (uint32_t)(st * BN * KPH + row * KPH + c * 8) * 2,
                          src, 16);
            }
        }
        cp_commit();
    };

    load_stage(0, 0);

    for (int kt = 0; kt < KT; kt++) {
        int st = kt & 1;
        if (kt + 1 < KT) {
            load_stage(st ^ 1, kt + 1);
            asm volatile("cp.async.wait_group 1;" ::: "memory");
        } else {
            asm volatile("cp.async.wait_group 0;" ::: "memory");
        }
        __syncthreads();

#pragma unroll
        for (int ks = 0; ks < 2; ks++) {
            int kb = ks * 16;
            uint32_t a[2][4], b[8][2];
            // A fragments (m16n8k16): a0={row g, k 2t..2t+1}, a1={row g+8, same},
            //                         a2={row g, k 2t+8..}, a3={row g+8, k 2t+8..}
#pragma unroll
            for (int i = 0; i < 2; i++) {
                int r0 = wm + i * 16;
                a[i][0] = *(const uint32_t*)&As[st][r0 + g][kb + 2 * t];
                a[i][1] = *(const uint32_t*)&As[st][r0 + g + 8][kb + 2 * t];
                a[i][2] = *(const uint32_t*)&As[st][r0 + g][kb + 2 * t + 8];
                a[i][3] = *(const uint32_t*)&As[st][r0 + g + 8][kb + 2 * t + 8];
            }
            // B fragments: b0={col g, k 2t..2t+1}, b1={col g, k 2t+8..2t+9}
#pragma unroll
            for (int j = 0; j < 8; j++) {
                int n0 = wn + j * 8;
                b[j][0] = *(const uint32_t*)&Bs[st][n0 + g][kb + 2 * t];
                b[j][1] = *(const uint32_t*)&Bs[st][n0 + g][kb + 2 * t + 8];
            }
#pragma unroll
            for (int i = 0; i < 2; i++)
#pragma unroll
                for (int j = 0; j < 8; j++) mma_f16(acc[i][j], a[i], b[j]);
        }
        __syncthreads();
    }

    // Epilogue: bias + activation, float2 stores
    const bool is_z = (bn < 512);  // cols [0,512) tanh; else sigmoid
#pragma unroll
    for (int i = 0; i < 2; i++) {
#pragma unroll
        for (int j = 0; j < 8; j++) {
            int col = bn + wn + j * 8 + 2 * t;
            float b0 = __ldg(bias + col), b1 = __ldg(bias + col + 1);
            int r0 = bm + wm + i * 16 + g;
            float2 v;
            v.x = acc[i][j][0] + b0;
            v.y = acc[i][j][1] + b1;
            v.x = is_z ? tanhf(v.x) : sigm(v.x);
            v.y = is_z ? tanhf(v.y) : sigm(v.y);
            *(float2*)(d_g + (size_t)r0 * Nc + col) = v;
            v.x = acc[i][j][2] + b0;
            v.y = acc[i][j][3] + b1;
            v.x = is_z ? tanhf(v.x) : sigm(v.x);
            v.y = is_z ? tanhf(v.y) : sigm(v.y);
            *(float2*)(d_g + (size_t)(r0 + 8) * Nc + col) = v;
        }
    }
}

// ---------------------------------------------------------------------------
// Scans (chunk-parallel linear recurrence), CHUNK=64
// ---------------------------------------------------------------------------
__global__ __launch_bounds__(512) void scan_chunk() {
    int dirch = threadIdx.x;
    int b = blockIdx.x >> 6;
    int ck = blockIdx.x & (NCH - 1);
    bool bwd = dirch >= OUTC;
    int base = ck * CHUNK;

    float c = 0.f, F = 1.f;
#pragma unroll 8
    for (int t = 0; t < CHUNK; t++) {
        int s = bwd ? (base + CHUNK - 1 - t) : (base + t);
        size_t row = (size_t)(b * Sc + s) * Nc;
        float z = d_g[row + dirch];
        float f = d_g[row + DCH + dirch];
        c = f * c + (1.f - f) * z;
        F *= f;
    }
    int idx = (b * NCH + ck) * DCH + dirch;
    d_F[idx] = F;
    d_C[idx] = c;
}

__global__ __launch_bounds__(512) void scan_heads() {
    int dirch = threadIdx.x;
    int b = blockIdx.x;
    bool bwd = dirch >= OUTC;

    float c = 0.f;
#pragma unroll
    for (int i = 0; i < NCH; i++) {
        int ck = bwd ? (NCH - 1 - i) : i;
        int idx = (b * NCH + ck) * DCH + dirch;
        d_cin[idx] = c;
        c = d_F[idx] * c + d_C[idx];
    }
}

__global__ __launch_bounds__(512) void scan_final(float* __restrict__ out) {
    int dirch = threadIdx.x;
    int b = blockIdx.x >> 6;
    int ck = blockIdx.x & (NCH - 1);
    bool bwd = dirch >= OUTC;
    int base = ck * CHUNK;

    float c = d_cin[(b * NCH + ck) * DCH + dirch];
#pragma unroll 8
    for (int t = 0; t < CHUNK; t++) {
        int s = bwd ? (base + CHUNK - 1 - t) : (base + t);
        size_t row = (size_t)(b * Sc + s);
        const float* gr = d_g + row * Nc;
        float z = gr[dirch];
        float f = gr[DCH + dirch];
        float o = gr[2 * DCH + dirch];
        c = f * c + (1.f - f) * z;
        out[row * DCH + dirch] = o * c;
    }
}

// ---------------------------------------------------------------------------
extern "C" void kernel_launch(void* const* d_in, const int* in_sizes, int n_in,
                              void* d_out, int out_size) {
    const float* x = (const float*)d_in[0];
    const float* W = (const float*)d_in[1];
    const float* bias = (const float*)d_in[2];
    float* out = (float*)d_out;

    conv_x<<<(Mc * Ic) / (256 * 4), 256>>>(x);        // 8192 blocks
    conv_w<<<(Nc * Kc) / (256 * 4), 256>>>(W);        // 768 blocks

    dim3 gg(Nc / BN, Mc / BM);  // (12, 256)
    gemm_mma<<<gg, 256>>>(bias);

    scan_chunk<<<Bc * NCH, 512>>>();
    scan_heads<<<Bc, 512>>>();
    scan_final<<<Bc * NCH, 512>>>(out);
}